// round 15
// baseline (speedup 1.0000x reference)
#include <cuda_runtime.h>
#include <cuda_fp16.h>

// Problem constants
#define B_TOTAL   16384
#define N_IN      6
#define N_MF      5
#define N_FUZZ    30      // N_IN * N_MF
#define N_RULES   2048
#define N_OUT     2

// Tiling: 64 rows/block, 4 rows per thread (uint2 = 2x half2), 256 blocks
// -> 2 co-resident blocks per SM (64 warps) for latency hiding.
#define THREADS   1024
#define ROWS      64
#define QUADS     16                    // ROWS/4
#define PARTS     64                    // THREADS / QUADS
#define RPP       (N_RULES / PARTS)     // 32 rules per thread
#define RED_GRP   16                    // stage-A groups per row

// Shared memory layout (dynamic). Reduction buffer OVERLAPS the rule buffer.
#define SMEM_FUZZ_BYTES   (N_FUZZ * QUADS * 8)            // 3840  (uint2 table)
#define SMEM_RULE_BYTES   (N_RULES * 16)                  // 32768
#define SMEM_RED_BYTES    (QUADS * PARTS * 12 * 4)        // 49152 (overlaps rules)
#define SMEM_RED2_BYTES   (ROWS * RED_GRP * 3 * 4)        // 12288
#define SMEM_TOTAL        (SMEM_FUZZ_BYTES + SMEM_RED_BYTES + SMEM_RED2_BYTES) // 65280

// ---------------------------------------------------------------------------
// Single fused kernel. 2 blocks/SM.
// ---------------------------------------------------------------------------
__global__ void __launch_bounds__(THREADS, 2) anfis_fused_kernel(
    const float* __restrict__ x,
    const float* __restrict__ mf_centers,
    const float* __restrict__ mf_scales,
    const float* __restrict__ out_centers,
    const int*   __restrict__ input_rules,
    const int*   __restrict__ output_rules,
    float* __restrict__ out)
{
    extern __shared__ char smem[];
    uint2*  s_fuzz  = reinterpret_cast<uint2*>(smem);                       // [30][16]
    float4* s_rules = reinterpret_cast<float4*>(smem + SMEM_FUZZ_BYTES);    // [2048] (dies after loop)
    float*  s_red   = reinterpret_cast<float*>(smem + SMEM_FUZZ_BYTES);     // overlaps rules
    float*  s_red2  = reinterpret_cast<float*>(smem + SMEM_FUZZ_BYTES + SMEM_RED_BYTES);

    const int tid  = threadIdx.x;
    const int quad = tid & (QUADS - 1);   // row-quad (0..15)
    const int part = tid >> 4;            // rule partition (0..63)

    // ---- phase 0: pack rules into smem (2 per thread) ----
#pragma unroll
    for (int rr = 0; rr < N_RULES / THREADS; rr++) {
        int r = tid + rr * THREADS;
        unsigned int b0 = 0, b1 = 0;
#pragma unroll
        for (int k = 0; k < 4; k++)
            b0 |= ((unsigned int)input_rules[r * N_IN + k] & 0xFFu) << (8 * k);
#pragma unroll
        for (int k = 0; k < 2; k++)
            b1 |= ((unsigned int)input_rules[r * N_IN + 4 + k] & 0xFFu) << (8 * k);
        float4 rv;
        rv.x = __uint_as_float(b0);
        rv.y = __uint_as_float(b1);
        rv.z = out_centers[output_rules[r * N_OUT + 0]];
        rv.w = out_centers[output_rules[r * N_OUT + 1]];
        s_rules[r] = rv;
    }

    // ---- phase 1: fuzzify — 1920 values across all threads ----
    if (tid < N_FUZZ * ROWS - THREADS || tid < THREADS) {  // always true; keep simple loop
        __half* fzh = reinterpret_cast<__half*>(s_fuzz);
        const int base_row = blockIdx.x * ROWS;
        for (int v = tid; v < N_FUZZ * ROWS; v += THREADS) {
            const int val = v >> 6;          // fuzz value id (0..29)
            const int row = v & (ROWS - 1);  // row in tile
            float xv = x[(base_row + row) * N_IN + val / N_MF];
            float z  = (xv - mf_centers[val]) / mf_scales[val];
            fzh[(val * QUADS + (row >> 2)) * 4 + (row & 3)] = __float2half_rn(__expf(-z * z));
        }
    }
    __syncthreads();

    // ---- phase 2: rule loop. LDS.64 gathers (conflict-free), hmin2 trees ----
    const uint2* fz = s_fuzz + quad;

    float l1a = 0.f, l1b = 0.f, l1c = 0.f, l1d = 0.f;
    float d0a = 0.f, d0b = 0.f, d0c = 0.f, d0d = 0.f;
    float d1a = 0.f, d1b = 0.f, d1c = 0.f, d1d = 0.f;

    const int rbeg = part * RPP;
#pragma unroll 4
    for (int r = rbeg; r < rbeg + RPP; r++) {
        float4 rv = s_rules[r];                         // half-warp-uniform LDS.128
        unsigned int b0 = __float_as_uint(rv.x);
        unsigned int b1 = __float_as_uint(rv.y);

        uint2 g0 = fz[__byte_perm(b0, 0, 0x4440) * QUADS];
        uint2 g1 = fz[__byte_perm(b0, 0, 0x4441) * QUADS];
        uint2 g2 = fz[__byte_perm(b0, 0, 0x4442) * QUADS];
        uint2 g3 = fz[__byte_perm(b0, 0, 0x4443) * QUADS];
        uint2 g4 = fz[__byte_perm(b1, 0, 0x4440) * QUADS];
        uint2 g5 = fz[__byte_perm(b1, 0, 0x4441) * QUADS];

        // tree-shaped min (3 levels) on both packed lanes
        __half2 mx = __hmin2(__hmin2(__hmin2(*(__half2*)&g0.x, *(__half2*)&g1.x),
                                     __hmin2(*(__half2*)&g2.x, *(__half2*)&g3.x)),
                             __hmin2(*(__half2*)&g4.x, *(__half2*)&g5.x));
        __half2 my = __hmin2(__hmin2(__hmin2(*(__half2*)&g0.y, *(__half2*)&g1.y),
                                     __hmin2(*(__half2*)&g2.y, *(__half2*)&g3.y)),
                             __hmin2(*(__half2*)&g4.y, *(__half2*)&g5.y));

        float2 wx = __half22float2(mx);
        float2 wy = __half22float2(my);

        l1a += wx.x;  l1b += wx.y;  l1c += wy.x;  l1d += wy.y;   // weights > 0
        d0a = fmaf(wx.x, rv.z, d0a);  d0b = fmaf(wx.y, rv.z, d0b);
        d0c = fmaf(wy.x, rv.z, d0c);  d0d = fmaf(wy.y, rv.z, d0d);
        d1a = fmaf(wx.x, rv.w, d1a);  d1b = fmaf(wx.y, rv.w, d1b);
        d1c = fmaf(wy.x, rv.w, d1c);  d1d = fmaf(wy.y, rv.w, d1d);
    }

    // Rules region is dead; reduction buffer overlaps it.
    __syncthreads();

    // ---- phase 3a: dump per-thread partials ----
    {
        float* dst = s_red + (quad * PARTS + part) * 12;
        dst[0] = l1a; dst[1]  = l1b; dst[2]  = l1c; dst[3]  = l1d;
        dst[4] = d0a; dst[5]  = d0b; dst[6]  = d0c; dst[7]  = d0d;
        dst[8] = d1a; dst[9]  = d1b; dst[10] = d1c; dst[11] = d1d;
    }
    __syncthreads();

    // ---- phase 3b: stage A — 1024 threads = 64 rows x 16 groups, 4 parts each ----
    {
        const int row = tid >> 4;            // 0..63
        const int k   = tid & (RED_GRP - 1); // group 0..15
        const int q   = row >> 2;
        const int sub = row & 3;
        float L = 0.f, D0 = 0.f, D1 = 0.f;
#pragma unroll
        for (int pp = 0; pp < PARTS / RED_GRP; pp++) {
            const float* src = s_red + (q * PARTS + (k * (PARTS / RED_GRP) + pp)) * 12;
            L  += src[0 + sub];
            D0 += src[4 + sub];
            D1 += src[8 + sub];
        }
        float* dst = s_red2 + (row * RED_GRP + k) * 3;
        dst[0] = L; dst[1] = D0; dst[2] = D1;
    }
    __syncthreads();

    // ---- phase 3c: stage B — 64 threads finish + tanh head ----
    if (tid < ROWS) {
        float L = 0.f, D0 = 0.f, D1 = 0.f;
#pragma unroll
        for (int k = 0; k < RED_GRP; k++) {
            const float* src = s_red2 + (tid * RED_GRP + k) * 3;
            L += src[0]; D0 += src[1]; D1 += src[2];
        }
        float inv = 1.0f / fmaxf(L, 1e-12f);
        const int grow = blockIdx.x * ROWS + tid;
        out[grow * 2 + 0] = tanhf(D0 * inv) * 4.0f;            // scale 4.0, center 0.0
        out[grow * 2 + 1] = tanhf(D1 * inv) * 0.75f + 0.75f;   // scale 0.75, center 0.75
    }
}

// ---------------------------------------------------------------------------
// Launch contract
// ---------------------------------------------------------------------------
extern "C" void kernel_launch(void* const* d_in, const int* in_sizes, int n_in,
                              void* d_out, int out_size)
{
    const float* x            = (const float*)d_in[0];
    const float* mf_centers   = (const float*)d_in[1];
    const float* mf_scales    = (const float*)d_in[2];
    const float* out_centers  = (const float*)d_in[3];
    const int*   input_rules  = (const int*)d_in[4];
    const int*   output_rules = (const int*)d_in[5];
    float*       out          = (float*)d_out;

    // Opt-in to >48KB dynamic smem (immediate API call; capture-safe, no alloc)
    static bool attr_set = false;
    if (!attr_set) {
        cudaFuncSetAttribute(anfis_fused_kernel,
                             cudaFuncAttributeMaxDynamicSharedMemorySize, SMEM_TOTAL);
        attr_set = true;
    }

    anfis_fused_kernel<<<B_TOTAL / ROWS, THREADS, SMEM_TOTAL>>>(
        x, mf_centers, mf_scales, out_centers, input_rules, output_rules, out);
}

// round 16
// speedup vs baseline: 1.1631x; 1.1631x over previous
#include <cuda_runtime.h>
#include <cuda_fp16.h>

// Problem constants
#define B_TOTAL   16384
#define N_IN      6
#define N_MF      5
#define N_FUZZ    30      // N_IN * N_MF
#define N_RULES   2048
#define N_OUT     2
#define NKEYS     (N_FUZZ * N_FUZZ)    // 900 sort buckets (i0*30+i1)

// Tiling: 128 rows/block, 4 rows per thread (uint2 = 2x half2), warp-uniform rules
#define THREADS   1024
#define ROWS      128
#define QUADS     32                    // ROWS/4
#define PARTS     32                    // THREADS/QUADS; part = tid>>5 (warp-uniform)
#define RPP       (N_RULES / PARTS)     // 64 rules per thread

// Shared memory layout (dynamic). Conflict-free padded reduction buffers.
#define RED_STRIDE        417                              // 32*13+1 words (odd)
#define SMEM_FUZZ_BYTES   (N_FUZZ * QUADS * 8)             // 7680 (uint2 table)
#define SMEM_RED_BYTES    (PARTS * RED_STRIDE * 4)         // 53376 (overlaps rules)
#define SMEM_RED2_BYTES   (ROWS * 25 * 4)                  // 12800
#define SMEM_TOTAL        (SMEM_FUZZ_BYTES + SMEM_RED_BYTES + SMEM_RED2_BYTES) // 73856

// Sorted packed rules: b0 = i0|i1<<8|i2<<16|i3<<24 ; b1 = i4|i5<<8 ; ow0; ow1
__device__ float4 g_rules[N_RULES];

// ---------------------------------------------------------------------------
// Pack + counting-sort rules by (i0, i1). One block, 1024 threads.
// ---------------------------------------------------------------------------
__global__ void __launch_bounds__(THREADS) pack_sort_kernel(
    const int*   __restrict__ input_rules,
    const int*   __restrict__ output_rules,
    const float* __restrict__ out_centers)
{
    __shared__ int s_cnt[NKEYS];
    __shared__ int s_wsum[32];
    const int tid  = threadIdx.x;
    const int lane = tid & 31;
    const int wid  = tid >> 5;

    for (int i = tid; i < NKEYS; i += THREADS) s_cnt[i] = 0;
    __syncthreads();

    int key[2];
#pragma unroll
    for (int rr = 0; rr < 2; rr++) {
        int r = tid + rr * THREADS;
        int i0 = input_rules[r * N_IN + 0];
        int i1 = input_rules[r * N_IN + 1];
        key[rr] = i0 * N_FUZZ + i1;
        atomicAdd(&s_cnt[key[rr]], 1);
    }
    __syncthreads();

    // block-wide exclusive scan over the 900 counts (1024-wide scan)
    int v = (tid < NKEYS) ? s_cnt[tid] : 0;
    int x = v;
#pragma unroll
    for (int d = 1; d < 32; d <<= 1) {
        int y = __shfl_up_sync(0xFFFFFFFFu, x, d);
        if (lane >= d) x += y;
    }
    if (lane == 31) s_wsum[wid] = x;
    __syncthreads();
    if (wid == 0) {
        int s = s_wsum[lane];
#pragma unroll
        for (int d = 1; d < 32; d <<= 1) {
            int y = __shfl_up_sync(0xFFFFFFFFu, s, d);
            if (lane >= d) s += y;
        }
        s_wsum[lane] = s;
    }
    __syncthreads();
    int excl = x - v + ((wid > 0) ? s_wsum[wid - 1] : 0);
    __syncthreads();
    if (tid < NKEYS) s_cnt[tid] = excl;   // becomes the scatter cursor
    __syncthreads();

    // scatter packed rules into sorted order
#pragma unroll
    for (int rr = 0; rr < 2; rr++) {
        int r = tid + rr * THREADS;
        unsigned int b0 = 0, b1 = 0;
#pragma unroll
        for (int k = 0; k < 4; k++)
            b0 |= ((unsigned int)input_rules[r * N_IN + k] & 0xFFu) << (8 * k);
#pragma unroll
        for (int k = 0; k < 2; k++)
            b1 |= ((unsigned int)input_rules[r * N_IN + 4 + k] & 0xFFu) << (8 * k);
        float4 rv;
        rv.x = __uint_as_float(b0);
        rv.y = __uint_as_float(b1);
        rv.z = out_centers[output_rules[r * N_OUT + 0]];
        rv.w = out_centers[output_rules[r * N_OUT + 1]];
        int pos = atomicAdd(&s_cnt[key[rr]], 1);
        g_rules[pos] = rv;
    }
}

// ---- packed f32x2 helpers (Blackwell FFMA2/FADD2) ----
__device__ __forceinline__ unsigned long long pack_f32x2(float lo, float hi) {
    unsigned long long r;
    asm("mov.b64 %0, {%1, %2};" : "=l"(r) : "f"(lo), "f"(hi));
    return r;
}
__device__ __forceinline__ void unpack_f32x2(unsigned long long v, float& lo, float& hi) {
    asm("mov.b64 {%0, %1}, %2;" : "=f"(lo), "=f"(hi) : "l"(v));
}
__device__ __forceinline__ void fma_f32x2(unsigned long long& d,
                                          unsigned long long a, unsigned long long b) {
    asm("fma.rn.f32x2 %0, %1, %2, %0;" : "+l"(d) : "l"(a), "l"(b));
}
__device__ __forceinline__ void add_f32x2(unsigned long long& d, unsigned long long a) {
    asm("add.rn.f32x2 %0, %1, %0;" : "+l"(d) : "l"(a));
}

// ---------------------------------------------------------------------------
// Main kernel: 128 rows x 2048 sorted rules per block, grid 128.
// ---------------------------------------------------------------------------
__global__ void __launch_bounds__(THREADS, 1) anfis_main_kernel(
    const float* __restrict__ x,
    const float* __restrict__ mf_centers,
    const float* __restrict__ mf_scales,
    float* __restrict__ out)
{
    extern __shared__ char smem[];
    uint2*  s_fuzz  = reinterpret_cast<uint2*>(smem);                       // [30][32]
    float4* s_rules = reinterpret_cast<float4*>(smem + SMEM_FUZZ_BYTES);    // [2048] (dies after loop)
    float*  s_red   = reinterpret_cast<float*>(smem + SMEM_FUZZ_BYTES);     // overlaps rules
    float*  s_red2  = reinterpret_cast<float*>(smem + SMEM_FUZZ_BYTES + SMEM_RED_BYTES);

    const int tid  = threadIdx.x;
    const int quad = tid & (QUADS - 1);   // row-quad (0..31) = lane
    const int part = tid >> 5;            // rule partition (0..31) = warp id

    // ---- stage sorted rules from global (L2) into smem: 2 float4 per thread ----
    {
        const float4* gr = g_rules;
        s_rules[tid]            = gr[tid];
        s_rules[tid + THREADS]  = gr[tid + THREADS];
    }

    // ---- fuzzify: all 1024 threads cover 30*128 values ----
    {
        __half* fzh = reinterpret_cast<__half*>(s_fuzz);
        const int base_row = blockIdx.x * ROWS;
#pragma unroll
        for (int v = tid; v < N_FUZZ * ROWS; v += THREADS) {
            const int val = v >> 7;          // fuzz value id (0..29)
            const int row = v & (ROWS - 1);  // row in tile
            float xv = x[(base_row + row) * N_IN + val / N_MF];
            float z  = (xv - mf_centers[val]) / mf_scales[val];
            fzh[(val * QUADS + (row >> 2)) * 4 + (row & 3)] = __float2half_rn(__expf(-z * z));
        }
    }
    __syncthreads();

    // ---- rule loop: sorted rules => i0 (and often i1) constant across iters.
    //      Cache their gathers behind warp-uniform compares. ----
    const uint2* fz = s_fuzz + quad;

    unsigned long long l1p0 = 0, l1p1 = 0;
    unsigned long long d0p0 = 0, d0p1 = 0;
    unsigned long long d1p0 = 0, d1p1 = 0;

    unsigned int ci0 = 0xFFFFFFFFu, ci1 = 0xFFFFFFFFu;
    uint2 c0 = make_uint2(0, 0), c1 = make_uint2(0, 0);

    const int rbeg = part * RPP;
#pragma unroll 2
    for (int r = rbeg; r < rbeg + RPP; r++) {
        float4 rv = s_rules[r];                       // warp-uniform LDS.128
        unsigned int b0 = __float_as_uint(rv.x);
        unsigned int b1 = __float_as_uint(rv.y);

        unsigned int i0 = b0 & 0xFFu;
        unsigned int i1 = __byte_perm(b0, 0, 0x4441);
        if (i0 != ci0) { c0 = fz[i0 * QUADS]; ci0 = i0; }   // warp-uniform branch
        if (i1 != ci1) { c1 = fz[i1 * QUADS]; ci1 = i1; }   // warp-uniform branch

        uint2 g2 = fz[__byte_perm(b0, 0, 0x4442) * QUADS];
        uint2 g3 = fz[__byte_perm(b0, 0, 0x4443) * QUADS];
        uint2 g4 = fz[(b1 & 0xFFu) * QUADS];
        uint2 g5 = fz[__byte_perm(b1, 0, 0x4441) * QUADS];

        __half2 mx = __hmin2(__hmin2(__hmin2(*(__half2*)&c0.x, *(__half2*)&c1.x),
                                     __hmin2(*(__half2*)&g2.x, *(__half2*)&g3.x)),
                             __hmin2(*(__half2*)&g4.x, *(__half2*)&g5.x));
        __half2 my = __hmin2(__hmin2(__hmin2(*(__half2*)&c0.y, *(__half2*)&c1.y),
                                     __hmin2(*(__half2*)&g2.y, *(__half2*)&g3.y)),
                             __hmin2(*(__half2*)&g4.y, *(__half2*)&g5.y));

        float2 wx = __half22float2(mx);
        float2 wy = __half22float2(my);

        unsigned long long w0 = pack_f32x2(wx.x, wx.y);
        unsigned long long w1 = pack_f32x2(wy.x, wy.y);
        unsigned long long z2 = pack_f32x2(rv.z, rv.z);
        unsigned long long w2 = pack_f32x2(rv.w, rv.w);

        add_f32x2(l1p0, w0);        add_f32x2(l1p1, w1);      // weights > 0
        fma_f32x2(d0p0, w0, z2);    fma_f32x2(d0p1, w1, z2);
        fma_f32x2(d1p0, w0, w2);    fma_f32x2(d1p1, w1, w2);
    }

    float l1a, l1b, l1c, l1d, d0a, d0b, d0c, d0d, d1a, d1b, d1c, d1d;
    unpack_f32x2(l1p0, l1a, l1b);  unpack_f32x2(l1p1, l1c, l1d);
    unpack_f32x2(d0p0, d0a, d0b);  unpack_f32x2(d0p1, d0c, d0d);
    unpack_f32x2(d1p0, d1a, d1b);  unpack_f32x2(d1p1, d1c, d1d);

    // Rules region is dead; padded reduction buffer overlaps it.
    __syncthreads();

    // ---- dump partials: lane stride 13 (odd) => conflict-free STS ----
    {
        float* dst = s_red + part * RED_STRIDE + quad * 13;
        dst[0] = l1a; dst[1]  = l1b; dst[2]  = l1c; dst[3]  = l1d;
        dst[4] = d0a; dst[5]  = d0b; dst[6]  = d0c; dst[7]  = d0d;
        dst[8] = d1a; dst[9]  = d1b; dst[10] = d1c; dst[11] = d1d;
    }
    __syncthreads();

    // ---- stage A: 1024 threads = 128 rows x 8 groups; each sums 4 partitions ----
    {
        const int row = tid >> 3;            // 0..127
        const int k   = tid & 7;             // group 0..7
        const int q   = row >> 2;
        const int sub = row & 3;
        float L = 0.f, D0 = 0.f, D1 = 0.f;
#pragma unroll
        for (int pp = 0; pp < 4; pp++) {
            const float* src = s_red + (k * 4 + pp) * RED_STRIDE + q * 13;
            L  += src[0 + sub];
            D0 += src[4 + sub];
            D1 += src[8 + sub];
        }
        float* dst = s_red2 + row * 25 + k * 3;
        dst[0] = L; dst[1] = D0; dst[2] = D1;
    }
    __syncthreads();

    // ---- stage B: 128 threads finish + tanh head ----
    if (tid < ROWS) {
        float L = 0.f, D0 = 0.f, D1 = 0.f;
#pragma unroll
        for (int k = 0; k < 8; k++) {
            const float* src = s_red2 + tid * 25 + k * 3;
            L += src[0]; D0 += src[1]; D1 += src[2];
        }
        float inv = 1.0f / fmaxf(L, 1e-12f);
        const int grow = blockIdx.x * ROWS + tid;
        out[grow * 2 + 0] = tanhf(D0 * inv) * 4.0f;            // scale 4.0, center 0.0
        out[grow * 2 + 1] = tanhf(D1 * inv) * 0.75f + 0.75f;   // scale 0.75, center 0.75
    }
}

// ---------------------------------------------------------------------------
// Launch contract
// ---------------------------------------------------------------------------
extern "C" void kernel_launch(void* const* d_in, const int* in_sizes, int n_in,
                              void* d_out, int out_size)
{
    const float* x            = (const float*)d_in[0];
    const float* mf_centers   = (const float*)d_in[1];
    const float* mf_scales    = (const float*)d_in[2];
    const float* out_centers  = (const float*)d_in[3];
    const int*   input_rules  = (const int*)d_in[4];
    const int*   output_rules = (const int*)d_in[5];
    float*       out          = (float*)d_out;

    // Opt-in to >48KB dynamic smem (immediate API call; capture-safe, no alloc)
    static bool attr_set = false;
    if (!attr_set) {
        cudaFuncSetAttribute(anfis_main_kernel,
                             cudaFuncAttributeMaxDynamicSharedMemorySize, SMEM_TOTAL);
        attr_set = true;
    }

    pack_sort_kernel<<<1, THREADS>>>(input_rules, output_rules, out_centers);
    anfis_main_kernel<<<B_TOTAL / ROWS, THREADS, SMEM_TOTAL>>>(x, mf_centers, mf_scales, out);
}